// round 12
// baseline (speedup 1.0000x reference)
#include <cuda_runtime.h>
#include <cuda_fp16.h>
#include <mma.h>

using namespace nvcuda;

#define NV 100000
#define NE 1600000
#define HID 64
#define FIN 256
#define TM 32
#define PADH 72
#define NTILES 3125     // NV / TM
#define TPB_T 4         // row-tiles per fused block
#define NBLK_SCAN 391   // ceil(NV/256)

// ---------------- scratch (static device globals) ---------------------------
__device__ float   g_ns[NV];
__device__ float   g_nd[NV];
__device__ int     g_odeg[NV];
__device__ int     g_indeg[NV];
__device__ int     g_rowptr[NV + 1];
__device__ int     g_cur[NV];
__device__ int     g_bsum[512];
__device__ int     g_boff[512];
__device__ int     g_esrc[NE];                   // src ids grouped by dst (CSR)
__device__ __half2 g_hs2[(size_t)NV * 32];       // fp16 message table (64 cols)
__device__ float   g_agg[(size_t)NV * HID];      // gather destination (fp32)
__device__ float   g_y[(size_t)NV * HID];        // accumulated out @ Wout (fp32)

// ---------------- degree / CSR build ----------------------------------------
__global__ void k_zero0() {
    int i = blockIdx.x * blockDim.x + threadIdx.x;
    if (i < NV) { g_odeg[i] = 0; g_indeg[i] = 0; }
}

__global__ void k_deg(const int* __restrict__ src, const int* __restrict__ dst) {
    int e = blockIdx.x * blockDim.x + threadIdx.x;
    if (e < NE) {
        atomicAdd(&g_odeg[src[e]], 1);
        atomicAdd(&g_indeg[dst[e]], 1);
    }
}

__global__ void k_norm() {
    int i = blockIdx.x * blockDim.x + threadIdx.x;
    if (i < NV) {
        g_ns[i] = rsqrtf(fmaxf((float)g_odeg[i], 1.f));
        g_nd[i] = rsqrtf(fmaxf((float)g_indeg[i], 1.f));
    }
}

__global__ void __launch_bounds__(256) k_scan1() {
    __shared__ int sm[256];
    int t = threadIdx.x;
    int i = blockIdx.x * 256 + t;
    int v = (i < NV) ? g_indeg[i] : 0;
    sm[t] = v;
    __syncthreads();
    #pragma unroll
    for (int ofs = 1; ofs < 256; ofs <<= 1) {
        int add = (t >= ofs) ? sm[t - ofs] : 0;
        __syncthreads();
        sm[t] += add;
        __syncthreads();
    }
    if (i < NV) g_rowptr[i] = sm[t] - v;
    if (t == 255) g_bsum[blockIdx.x] = sm[255];
}

__global__ void __launch_bounds__(512) k_scan2() {
    __shared__ int sm[512];
    int t = threadIdx.x;
    int v = (t < NBLK_SCAN) ? g_bsum[t] : 0;
    sm[t] = v;
    __syncthreads();
    #pragma unroll
    for (int ofs = 1; ofs < 512; ofs <<= 1) {
        int add = (t >= ofs) ? sm[t - ofs] : 0;
        __syncthreads();
        sm[t] += add;
        __syncthreads();
    }
    g_boff[t] = sm[t] - v;
}

__global__ void k_scan3() {
    int i = blockIdx.x * blockDim.x + threadIdx.x;
    if (i < NV) {
        int r = g_rowptr[i] + g_boff[i >> 8];
        g_rowptr[i] = r;
        g_cur[i] = r;
    }
    if (i == 0) g_rowptr[NV] = NE;
}

__global__ void k_fill(const int* __restrict__ src, const int* __restrict__ dst) {
    int e = blockIdx.x * blockDim.x + threadIdx.x;
    if (e < NE) {
        int pos = atomicAdd(&g_cur[dst[e]], 1);
        g_esrc[pos] = src[e];
    }
}

// ---------------- CSR gather hs (fp16 table -> fp32 accum) --------------------
__global__ void __launch_bounds__(256)
k_gather_hs() {
    int w = (blockIdx.x * 256 + threadIdx.x) >> 5;
    int lane = threadIdx.x & 31;
    if (w >= NV) return;
    int beg = g_rowptr[w], end = g_rowptr[w + 1];
    float2 acc = make_float2(0.f, 0.f);
    int e = beg;
    for (; e + 4 <= end; e += 4) {
        int s0 = g_esrc[e], s1 = g_esrc[e + 1], s2 = g_esrc[e + 2], s3 = g_esrc[e + 3];
        float2 v0 = __half22float2(g_hs2[(size_t)s0 * 32 + lane]);
        float2 v1 = __half22float2(g_hs2[(size_t)s1 * 32 + lane]);
        float2 v2 = __half22float2(g_hs2[(size_t)s2 * 32 + lane]);
        float2 v3 = __half22float2(g_hs2[(size_t)s3 * 32 + lane]);
        acc.x += (v0.x + v1.x) + (v2.x + v3.x);
        acc.y += (v0.y + v1.y) + (v2.y + v3.y);
    }
    for (; e < end; e++) {
        int s = g_esrc[e];
        float2 v = __half22float2(g_hs2[(size_t)s * 32 + lane]);
        acc.x += v.x; acc.y += v.y;
    }
    reinterpret_cast<float2*>(g_agg)[(size_t)w * 32 + lane] = acc;
}

// final: out[n] = bout + sum g_y[esrc[e]]   (fp32 table)
__global__ void __launch_bounds__(256)
k_gather_out(float* __restrict__ out, const float* __restrict__ bout) {
    int w = (blockIdx.x * 256 + threadIdx.x) >> 5;
    int lane = threadIdx.x & 31;
    if (w >= NV) return;
    int beg = g_rowptr[w], end = g_rowptr[w + 1];
    const float2* tb = reinterpret_cast<const float2*>(g_y);
    float2 acc = reinterpret_cast<const float2*>(bout)[lane];
    int e = beg;
    for (; e + 4 <= end; e += 4) {
        int s0 = g_esrc[e], s1 = g_esrc[e + 1], s2 = g_esrc[e + 2], s3 = g_esrc[e + 3];
        float2 v0 = tb[(size_t)s0 * 32 + lane];
        float2 v1 = tb[(size_t)s1 * 32 + lane];
        float2 v2 = tb[(size_t)s2 * 32 + lane];
        float2 v3 = tb[(size_t)s3 * 32 + lane];
        acc.x += (v0.x + v1.x) + (v2.x + v3.x);
        acc.y += (v0.y + v1.y) + (v2.y + v3.y);
    }
    for (; e < end; e++) {
        int s = g_esrc[e];
        float2 v = tb[(size_t)s * 32 + lane];
        acc.x += v.x; acc.y += v.y;
    }
    reinterpret_cast<float2*>(out)[(size_t)w * 32 + lane] = acc;
}

// ---------------- GEMM 0 (WMMA + A-prefetch): hs = ns*(feats @ W0) -----------
__global__ void __launch_bounds__(128)
k_gemm0(const float* __restrict__ feats, const float* __restrict__ W0) {
    __shared__ alignas(32) __half Ah[64][PADH];
    __shared__ alignas(32) __half Bh[64][PADH];
    __shared__ alignas(32) float  Cs[64][68];
    int t = threadIdx.x;
    int warp = t >> 5;
    int rowBase = blockIdx.x * 64;

    wmma::fragment<wmma::accumulator, 16, 16, 16, float> cf[4];
    #pragma unroll
    for (int i = 0; i < 4; i++) wmma::fill_fragment(cf[i], 0.0f);

    // A addressing per thread (8 float4 per chunk)
    int am[8], ak[8];
    #pragma unroll
    for (int i = 0; i < 8; i++) {
        int idx = t + i * 128;
        am[i] = idx >> 4;
        ak[i] = (idx & 15) * 4;
    }

    float4 pa[8];
    #pragma unroll
    for (int i = 0; i < 8; i++) {
        int rc = rowBase + am[i]; if (rc >= NV) rc = NV - 1;
        pa[i] = *reinterpret_cast<const float4*>(feats + (size_t)rc * FIN + ak[i]);
    }

    for (int kb = 0; kb < FIN; kb += 64) {
        #pragma unroll
        for (int i = 0; i < 8; i++) {               // commit prefetched A -> smem fp16
            __half2* dst = reinterpret_cast<__half2*>(&Ah[am[i]][ak[i]]);
            dst[0] = __floats2half2_rn(pa[i].x, pa[i].y);
            dst[1] = __floats2half2_rn(pa[i].z, pa[i].w);
        }
        #pragma unroll
        for (int i = 0; i < 8; i++) {               // B chunk 64x64 fp32->half (L2-hot)
            int idx = t + i * 128;
            int k = idx >> 4, c4 = (idx & 15) * 4;
            float4 b = *reinterpret_cast<const float4*>(W0 + (size_t)(kb + k) * HID + c4);
            __half2* dst = reinterpret_cast<__half2*>(&Bh[k][c4]);
            dst[0] = __floats2half2_rn(b.x, b.y);
            dst[1] = __floats2half2_rn(b.z, b.w);
        }
        __syncthreads();
        if (kb + 64 < FIN) {                        // prefetch next A chunk (overlaps MMA)
            #pragma unroll
            for (int i = 0; i < 8; i++) {
                int rc = rowBase + am[i]; if (rc >= NV) rc = NV - 1;
                pa[i] = *reinterpret_cast<const float4*>(feats + (size_t)rc * FIN + kb + 64 + ak[i]);
            }
        }
        #pragma unroll
        for (int ks = 0; ks < 4; ks++) {
            wmma::fragment<wmma::matrix_b, 16, 16, 16, __half, wmma::row_major> bf;
            wmma::load_matrix_sync(bf, &Bh[ks * 16][warp * 16], PADH);
            #pragma unroll
            for (int rt = 0; rt < 4; rt++) {
                wmma::fragment<wmma::matrix_a, 16, 16, 16, __half, wmma::row_major> af;
                wmma::load_matrix_sync(af, &Ah[rt * 16][ks * 16], PADH);
                wmma::mma_sync(cf[rt], af, bf, cf[rt]);
            }
        }
        __syncthreads();
    }
    #pragma unroll
    for (int rt = 0; rt < 4; rt++)
        wmma::store_matrix_sync(&Cs[rt * 16][warp * 16], cf[rt], 68, wmma::mem_row_major);
    __syncthreads();
    #pragma unroll
    for (int i = 0; i < 8; i++) {
        int idx = t + i * 128;
        int m = idx >> 4, c4 = (idx & 15) * 4;
        int row = rowBase + m;
        if (row < NV) {
            float s = g_ns[row];
            float4 v = *reinterpret_cast<const float4*>(&Cs[m][c4]);
            __half2* hp = &g_hs2[(size_t)row * 32 + (c4 >> 1)];
            hp[0] = __floats2half2_rn(v.x * s, v.y * s);
            hp[1] = __floats2half2_rn(v.z * s, v.w * s);
        }
    }
}

// ---------------- fused layer GEMM (WMMA, multi-tile, B loaded once) ---------
// Each block converts [W|Wo] to fp16 once, then processes TPB_T row-tiles.
__global__ void __launch_bounds__(128)
k_gemm_fused(const float* __restrict__ bias,
             const float* __restrict__ W,
             const float* __restrict__ Wo,
             int hasW, int firstY) {
    __shared__ alignas(32) __half Ah[TM][PADH];
    __shared__ alignas(32) __half Bwh[64][PADH];
    __shared__ alignas(32) __half Boh[64][PADH];
    __shared__ alignas(32) float  Cs[TM][132];
    int t = threadIdx.x;
    int warp = t >> 5;

    // convert weights once per block
    if (hasW) {
        #pragma unroll
        for (int i = 0; i < 8; i++) {
            int idx = t + i * 128;
            int k = idx >> 4, c4 = (idx & 15) * 4;
            float4 b = *reinterpret_cast<const float4*>(W + (size_t)k * HID + c4);
            __half2* dst = reinterpret_cast<__half2*>(&Bwh[k][c4]);
            dst[0] = __floats2half2_rn(b.x, b.y);
            dst[1] = __floats2half2_rn(b.z, b.w);
        }
    }
    #pragma unroll
    for (int i = 0; i < 8; i++) {
        int idx = t + i * 128;
        int k = idx >> 4, c4 = (idx & 15) * 4;
        float4 b = *reinterpret_cast<const float4*>(Wo + (size_t)k * HID + c4);
        __half2* dst = reinterpret_cast<__half2*>(&Boh[k][c4]);
        dst[0] = __floats2half2_rn(b.x, b.y);
        dst[1] = __floats2half2_rn(b.z, b.w);
    }
    __syncthreads();

    for (int tt = 0; tt < TPB_T; tt++) {
        int tile = blockIdx.x * TPB_T + tt;
        if (tile >= NTILES) break;
        int rowBase = tile * TM;

        #pragma unroll
        for (int i = 0; i < 4; i++) {               // A 32x64 relu-transform -> half
            int idx = t + i * 128;
            int m = idx >> 4, k4 = (idx & 15) * 4;
            int row = rowBase + m;
            float4 v = *reinterpret_cast<const float4*>(g_agg + (size_t)row * HID + k4);
            float nd = g_nd[row];
            float4 bb = *reinterpret_cast<const float4*>(bias + k4);
            __half2* dst = reinterpret_cast<__half2*>(&Ah[m][k4]);
            dst[0] = __floats2half2_rn(fmaxf(v.x * nd + bb.x, 0.f), fmaxf(v.y * nd + bb.y, 0.f));
            dst[1] = __floats2half2_rn(fmaxf(v.z * nd + bb.z, 0.f), fmaxf(v.w * nd + bb.w, 0.f));
        }
        __syncthreads();

        wmma::fragment<wmma::accumulator, 16, 16, 16, float> cw[2], co[2];
        #pragma unroll
        for (int i = 0; i < 2; i++) {
            wmma::fill_fragment(cw[i], 0.0f);
            wmma::fill_fragment(co[i], 0.0f);
        }

        #pragma unroll
        for (int ks = 0; ks < 4; ks++) {
            wmma::fragment<wmma::matrix_a, 16, 16, 16, __half, wmma::row_major> af[2];
            #pragma unroll
            for (int rt = 0; rt < 2; rt++)
                wmma::load_matrix_sync(af[rt], &Ah[rt * 16][ks * 16], PADH);
            if (hasW) {
                wmma::fragment<wmma::matrix_b, 16, 16, 16, __half, wmma::row_major> bw;
                wmma::load_matrix_sync(bw, &Bwh[ks * 16][warp * 16], PADH);
                #pragma unroll
                for (int rt = 0; rt < 2; rt++)
                    wmma::mma_sync(cw[rt], af[rt], bw, cw[rt]);
            }
            wmma::fragment<wmma::matrix_b, 16, 16, 16, __half, wmma::row_major> bo;
            wmma::load_matrix_sync(bo, &Boh[ks * 16][warp * 16], PADH);
            #pragma unroll
            for (int rt = 0; rt < 2; rt++)
                wmma::mma_sync(co[rt], af[rt], bo, co[rt]);
        }

        #pragma unroll
        for (int rt = 0; rt < 2; rt++) {
            if (hasW)
                wmma::store_matrix_sync(&Cs[rt * 16][warp * 16], cw[rt], 132, wmma::mem_row_major);
            wmma::store_matrix_sync(&Cs[rt * 16][64 + warp * 16], co[rt], 132, wmma::mem_row_major);
        }
        __syncthreads();

        if (hasW) {
            #pragma unroll
            for (int i = 0; i < 4; i++) {
                int idx = t + i * 128;
                int m = idx >> 4, c4 = (idx & 15) * 4;
                int row = rowBase + m;
                float s = g_ns[row];
                float4 v = *reinterpret_cast<const float4*>(&Cs[m][c4]);
                __half2* hp = &g_hs2[(size_t)row * 32 + (c4 >> 1)];
                hp[0] = __floats2half2_rn(v.x * s, v.y * s);
                hp[1] = __floats2half2_rn(v.z * s, v.w * s);
            }
        }
        #pragma unroll
        for (int i = 0; i < 4; i++) {
            int idx = t + i * 128;
            int m = idx >> 4, c4 = (idx & 15) * 4;
            int row = rowBase + m;
            float4 v = *reinterpret_cast<const float4*>(&Cs[m][64 + c4]);
            float4* yp = reinterpret_cast<float4*>(g_y + (size_t)row * HID + c4);
            if (firstY) {
                *yp = v;
            } else {
                float4 a = *yp;
                a.x += v.x; a.y += v.y; a.z += v.z; a.w += v.w;
                *yp = a;
            }
        }
        __syncthreads();
    }
}

// ---------------- launch ------------------------------------------------------
extern "C" void kernel_launch(void* const* d_in, const int* in_sizes, int n_in,
                              void* d_out, int out_size) {
    const float* feats = (const float*)d_in[0];
    const int*   src   = (const int*)d_in[1];
    const int*   dst   = (const int*)d_in[2];
    const float* W[5];
    const float* B[5];
    for (int i = 0; i < 5; i++) {
        W[i] = (const float*)d_in[3 + 2 * i];
        B[i] = (const float*)d_in[4 + 2 * i];
    }
    const float* Wout = (const float*)d_in[13];
    const float* bout = (const float*)d_in[14];
    float* out = (float*)d_out;

    const int TPB = 256;
    const int NB_V = (NV + TPB - 1) / TPB;      // 391
    const int NB_E = (NE + TPB - 1) / TPB;      // 6250
    const int NB_G = (NV * 32 + TPB - 1) / TPB; // 12500 (warp per node)
    const int NB_F = (NTILES + TPB_T - 1) / TPB_T;  // 782

    // prologue (gemm0 kept in the ncu-sampled 4th slot)
    k_zero0<<<NB_V, TPB>>>();
    k_deg<<<NB_E, TPB>>>(src, dst);
    k_norm<<<NB_V, TPB>>>();
    k_gemm0<<<(NV + 63) / 64, 128>>>(feats, W[0]);

    // CSR build (independent of gemm0)
    k_scan1<<<NB_V, 256>>>();
    k_scan2<<<1, 512>>>();
    k_scan3<<<NB_V, TPB>>>();
    k_fill<<<NB_E, TPB>>>(src, dst);

    // 5 message-passing layers
    for (int l = 0; l < 5; l++) {
        k_gather_hs<<<NB_G, TPB>>>();
        int hasW = (l < 4) ? 1 : 0;
        k_gemm_fused<<<NB_F, 128>>>(B[l],
                                    hasW ? W[l + 1] : W[0],
                                    Wout + (size_t)l * HID * 64,
                                    hasW, l == 0 ? 1 : 0);
    }

    // final aggregation straight into out (+bout)
    k_gather_out<<<NB_G, TPB>>>(out, bout);
}

// round 13
// speedup vs baseline: 1.0991x; 1.0991x over previous
#include <cuda_runtime.h>
#include <cuda_fp16.h>
#include <mma.h>

using namespace nvcuda;

#define NV 100000
#define NE 1600000
#define HID 64
#define FIN 256
#define TM 32
#define PADH 72
#define NBLK_SCAN 391   // ceil(NV/256)

// ---------------- scratch (static device globals) ---------------------------
__device__ float   g_ns[NV];
__device__ float   g_nd[NV];
__device__ int     g_odeg[NV];
__device__ int     g_indeg[NV];
__device__ int     g_rowptr[NV + 1];
__device__ int     g_cur[NV];
__device__ int     g_bsum[512];
__device__ int     g_boff[512];
__device__ int     g_esrc[NE];                   // src ids grouped by dst (CSR)
__device__ __half2 g_hs2[(size_t)NV * 32];       // fp16 message table (64 cols)
__device__ float   g_agg[(size_t)NV * HID];      // gather destination (fp32)
__device__ float   g_y[(size_t)NV * HID];        // accumulated out @ Wout (fp32)

// ---------------- degree / CSR build ----------------------------------------
__global__ void k_zero0() {
    int i = blockIdx.x * blockDim.x + threadIdx.x;
    if (i < NV) { g_odeg[i] = 0; g_indeg[i] = 0; }
}

__global__ void k_deg(const int* __restrict__ src, const int* __restrict__ dst) {
    int e = blockIdx.x * blockDim.x + threadIdx.x;
    if (e < NE) {
        atomicAdd(&g_odeg[src[e]], 1);
        atomicAdd(&g_indeg[dst[e]], 1);
    }
}

__global__ void k_norm() {
    int i = blockIdx.x * blockDim.x + threadIdx.x;
    if (i < NV) {
        g_ns[i] = rsqrtf(fmaxf((float)g_odeg[i], 1.f));
        g_nd[i] = rsqrtf(fmaxf((float)g_indeg[i], 1.f));
    }
}

__global__ void __launch_bounds__(256) k_scan1() {
    __shared__ int sm[256];
    int t = threadIdx.x;
    int i = blockIdx.x * 256 + t;
    int v = (i < NV) ? g_indeg[i] : 0;
    sm[t] = v;
    __syncthreads();
    #pragma unroll
    for (int ofs = 1; ofs < 256; ofs <<= 1) {
        int add = (t >= ofs) ? sm[t - ofs] : 0;
        __syncthreads();
        sm[t] += add;
        __syncthreads();
    }
    if (i < NV) g_rowptr[i] = sm[t] - v;
    if (t == 255) g_bsum[blockIdx.x] = sm[255];
}

__global__ void __launch_bounds__(512) k_scan2() {
    __shared__ int sm[512];
    int t = threadIdx.x;
    int v = (t < NBLK_SCAN) ? g_bsum[t] : 0;
    sm[t] = v;
    __syncthreads();
    #pragma unroll
    for (int ofs = 1; ofs < 512; ofs <<= 1) {
        int add = (t >= ofs) ? sm[t - ofs] : 0;
        __syncthreads();
        sm[t] += add;
        __syncthreads();
    }
    g_boff[t] = sm[t] - v;
}

__global__ void k_scan3() {
    int i = blockIdx.x * blockDim.x + threadIdx.x;
    if (i < NV) {
        int r = g_rowptr[i] + g_boff[i >> 8];
        g_rowptr[i] = r;
        g_cur[i] = r;
    }
    if (i == 0) g_rowptr[NV] = NE;
}

__global__ void k_fill(const int* __restrict__ src, const int* __restrict__ dst) {
    int e = blockIdx.x * blockDim.x + threadIdx.x;
    if (e < NE) {
        int pos = atomicAdd(&g_cur[dst[e]], 1);
        g_esrc[pos] = src[e];
    }
}

// ---------------- CSR gather hs: 4 edges per warp-LDG (fp16 rows, 128B) ------
// warp = node; 4 groups of 8 lanes; lane loads 16B (8 halves) of its edge.
__global__ void __launch_bounds__(256)
k_gather_hs() {
    int w = (blockIdx.x * 256 + threadIdx.x) >> 5;
    int lane = threadIdx.x & 31;
    if (w >= NV) return;
    int g = lane >> 3, l8 = lane & 7;
    int beg = g_rowptr[w], end = g_rowptr[w + 1];
    const uint4* tb = reinterpret_cast<const uint4*>(g_hs2);
    float acc[8] = {0.f, 0.f, 0.f, 0.f, 0.f, 0.f, 0.f, 0.f};

    int e = beg + g;
    for (; e + 4 < end; e += 8) {             // unroll 2: both loads in flight
        int s0 = __ldg(g_esrc + e);
        int s1 = __ldg(g_esrc + e + 4);
        uint4 v0 = tb[(size_t)s0 * 8 + l8];
        uint4 v1 = tb[(size_t)s1 * 8 + l8];
        const __half2* h0 = reinterpret_cast<const __half2*>(&v0);
        const __half2* h1 = reinterpret_cast<const __half2*>(&v1);
        #pragma unroll
        for (int j = 0; j < 4; j++) {
            float2 f0 = __half22float2(h0[j]);
            float2 f1 = __half22float2(h1[j]);
            acc[2 * j]     += f0.x + f1.x;
            acc[2 * j + 1] += f0.y + f1.y;
        }
    }
    if (e < end) {
        int s = __ldg(g_esrc + e);
        uint4 v = tb[(size_t)s * 8 + l8];
        const __half2* h = reinterpret_cast<const __half2*>(&v);
        #pragma unroll
        for (int j = 0; j < 4; j++) {
            float2 f = __half22float2(h[j]);
            acc[2 * j]     += f.x;
            acc[2 * j + 1] += f.y;
        }
    }
    // combine the 4 groups (butterfly leaves sum in all lanes)
    #pragma unroll
    for (int j = 0; j < 8; j++) {
        acc[j] += __shfl_xor_sync(0xffffffffu, acc[j], 8);
        acc[j] += __shfl_xor_sync(0xffffffffu, acc[j], 16);
    }
    if (lane < 8) {
        float4* dst = reinterpret_cast<float4*>(g_agg + (size_t)w * HID + l8 * 8);
        dst[0] = make_float4(acc[0], acc[1], acc[2], acc[3]);
        dst[1] = make_float4(acc[4], acc[5], acc[6], acc[7]);
    }
}

// ---------------- final gather: 2 edges per warp-LDG (fp32 rows, 256B) -------
__global__ void __launch_bounds__(256)
k_gather_out(float* __restrict__ out, const float* __restrict__ bout) {
    int w = (blockIdx.x * 256 + threadIdx.x) >> 5;
    int lane = threadIdx.x & 31;
    if (w >= NV) return;
    int g = lane >> 4, l16 = lane & 15;
    int beg = g_rowptr[w], end = g_rowptr[w + 1];
    const float4* tb = reinterpret_cast<const float4*>(g_y);
    float4 acc = make_float4(0.f, 0.f, 0.f, 0.f);

    int e = beg + g;
    for (; e + 2 < end; e += 4) {             // unroll 2
        int s0 = __ldg(g_esrc + e);
        int s1 = __ldg(g_esrc + e + 2);
        float4 v0 = tb[(size_t)s0 * 16 + l16];
        float4 v1 = tb[(size_t)s1 * 16 + l16];
        acc.x += v0.x + v1.x; acc.y += v0.y + v1.y;
        acc.z += v0.z + v1.z; acc.w += v0.w + v1.w;
    }
    if (e < end) {
        int s = __ldg(g_esrc + e);
        float4 v = tb[(size_t)s * 16 + l16];
        acc.x += v.x; acc.y += v.y; acc.z += v.z; acc.w += v.w;
    }
    acc.x += __shfl_xor_sync(0xffffffffu, acc.x, 16);
    acc.y += __shfl_xor_sync(0xffffffffu, acc.y, 16);
    acc.z += __shfl_xor_sync(0xffffffffu, acc.z, 16);
    acc.w += __shfl_xor_sync(0xffffffffu, acc.w, 16);
    if (lane < 16) {
        float4 b = reinterpret_cast<const float4*>(bout)[l16];
        acc.x += b.x; acc.y += b.y; acc.z += b.z; acc.w += b.w;
        reinterpret_cast<float4*>(out)[(size_t)w * 16 + l16] = acc;
    }
}

// ---------------- GEMM 0 (WMMA + A-prefetch): hs = ns*(feats @ W0) -----------
__global__ void __launch_bounds__(128)
k_gemm0(const float* __restrict__ feats, const float* __restrict__ W0) {
    __shared__ alignas(32) __half Ah[64][PADH];
    __shared__ alignas(32) __half Bh[64][PADH];
    __shared__ alignas(32) float  Cs[64][68];
    int t = threadIdx.x;
    int warp = t >> 5;
    int rowBase = blockIdx.x * 64;

    wmma::fragment<wmma::accumulator, 16, 16, 16, float> cf[4];
    #pragma unroll
    for (int i = 0; i < 4; i++) wmma::fill_fragment(cf[i], 0.0f);

    int am[8], ak[8];
    #pragma unroll
    for (int i = 0; i < 8; i++) {
        int idx = t + i * 128;
        am[i] = idx >> 4;
        ak[i] = (idx & 15) * 4;
    }

    float4 pa[8];
    #pragma unroll
    for (int i = 0; i < 8; i++) {
        int rc = rowBase + am[i]; if (rc >= NV) rc = NV - 1;
        pa[i] = *reinterpret_cast<const float4*>(feats + (size_t)rc * FIN + ak[i]);
    }

    for (int kb = 0; kb < FIN; kb += 64) {
        #pragma unroll
        for (int i = 0; i < 8; i++) {
            __half2* dst = reinterpret_cast<__half2*>(&Ah[am[i]][ak[i]]);
            dst[0] = __floats2half2_rn(pa[i].x, pa[i].y);
            dst[1] = __floats2half2_rn(pa[i].z, pa[i].w);
        }
        #pragma unroll
        for (int i = 0; i < 8; i++) {
            int idx = t + i * 128;
            int k = idx >> 4, c4 = (idx & 15) * 4;
            float4 b = *reinterpret_cast<const float4*>(W0 + (size_t)(kb + k) * HID + c4);
            __half2* dst = reinterpret_cast<__half2*>(&Bh[k][c4]);
            dst[0] = __floats2half2_rn(b.x, b.y);
            dst[1] = __floats2half2_rn(b.z, b.w);
        }
        __syncthreads();
        if (kb + 64 < FIN) {
            #pragma unroll
            for (int i = 0; i < 8; i++) {
                int rc = rowBase + am[i]; if (rc >= NV) rc = NV - 1;
                pa[i] = *reinterpret_cast<const float4*>(feats + (size_t)rc * FIN + kb + 64 + ak[i]);
            }
        }
        #pragma unroll
        for (int ks = 0; ks < 4; ks++) {
            wmma::fragment<wmma::matrix_b, 16, 16, 16, __half, wmma::row_major> bf;
            wmma::load_matrix_sync(bf, &Bh[ks * 16][warp * 16], PADH);
            #pragma unroll
            for (int rt = 0; rt < 4; rt++) {
                wmma::fragment<wmma::matrix_a, 16, 16, 16, __half, wmma::row_major> af;
                wmma::load_matrix_sync(af, &Ah[rt * 16][ks * 16], PADH);
                wmma::mma_sync(cf[rt], af, bf, cf[rt]);
            }
        }
        __syncthreads();
    }
    #pragma unroll
    for (int rt = 0; rt < 4; rt++)
        wmma::store_matrix_sync(&Cs[rt * 16][warp * 16], cf[rt], 68, wmma::mem_row_major);
    __syncthreads();
    #pragma unroll
    for (int i = 0; i < 8; i++) {
        int idx = t + i * 128;
        int m = idx >> 4, c4 = (idx & 15) * 4;
        int row = rowBase + m;
        if (row < NV) {
            float s = g_ns[row];
            float4 v = *reinterpret_cast<const float4*>(&Cs[m][c4]);
            __half2* hp = &g_hs2[(size_t)row * 32 + (c4 >> 1)];
            hp[0] = __floats2half2_rn(v.x * s, v.y * s);
            hp[1] = __floats2half2_rn(v.z * s, v.w * s);
        }
    }
}

// ---------------- fused layer GEMM (WMMA, R11 per-tile form) -----------------
__global__ void __launch_bounds__(128)
k_gemm_fused(const float* __restrict__ bias,
             const float* __restrict__ W,
             const float* __restrict__ Wo,
             int hasW, int firstY) {
    __shared__ alignas(32) __half Ah[TM][PADH];
    __shared__ alignas(32) __half Bwh[64][PADH];
    __shared__ alignas(32) __half Boh[64][PADH];
    __shared__ alignas(32) float  Cs[TM][132];
    int t = threadIdx.x;
    int warp = t >> 5;
    int rowBase = blockIdx.x * TM;

    #pragma unroll
    for (int i = 0; i < 4; i++) {
        int idx = t + i * 128;
        int m = idx >> 4, k4 = (idx & 15) * 4;
        int row = rowBase + m;
        float4 v = *reinterpret_cast<const float4*>(g_agg + (size_t)row * HID + k4);
        float nd = g_nd[row];
        float4 bb = *reinterpret_cast<const float4*>(bias + k4);
        __half2* dst = reinterpret_cast<__half2*>(&Ah[m][k4]);
        dst[0] = __floats2half2_rn(fmaxf(v.x * nd + bb.x, 0.f), fmaxf(v.y * nd + bb.y, 0.f));
        dst[1] = __floats2half2_rn(fmaxf(v.z * nd + bb.z, 0.f), fmaxf(v.w * nd + bb.w, 0.f));
    }
    if (hasW) {
        #pragma unroll
        for (int i = 0; i < 8; i++) {
            int idx = t + i * 128;
            int k = idx >> 4, c4 = (idx & 15) * 4;
            float4 b = *reinterpret_cast<const float4*>(W + (size_t)k * HID + c4);
            __half2* dst = reinterpret_cast<__half2*>(&Bwh[k][c4]);
            dst[0] = __floats2half2_rn(b.x, b.y);
            dst[1] = __floats2half2_rn(b.z, b.w);
        }
    }
    #pragma unroll
    for (int i = 0; i < 8; i++) {
        int idx = t + i * 128;
        int k = idx >> 4, c4 = (idx & 15) * 4;
        float4 b = *reinterpret_cast<const float4*>(Wo + (size_t)k * HID + c4);
        __half2* dst = reinterpret_cast<__half2*>(&Boh[k][c4]);
        dst[0] = __floats2half2_rn(b.x, b.y);
        dst[1] = __floats2half2_rn(b.z, b.w);
    }
    __syncthreads();

    wmma::fragment<wmma::accumulator, 16, 16, 16, float> cw[2], co[2];
    #pragma unroll
    for (int i = 0; i < 2; i++) {
        wmma::fill_fragment(cw[i], 0.0f);
        wmma::fill_fragment(co[i], 0.0f);
    }

    #pragma unroll
    for (int ks = 0; ks < 4; ks++) {
        wmma::fragment<wmma::matrix_a, 16, 16, 16, __half, wmma::row_major> af[2];
        #pragma unroll
        for (int rt = 0; rt < 2; rt++)
            wmma::load_matrix_sync(af[rt], &Ah[rt * 16][ks * 16], PADH);
        if (hasW) {
            wmma::fragment<wmma::matrix_b, 16, 16, 16, __half, wmma::row_major> bw;
            wmma::load_matrix_sync(bw, &Bwh[ks * 16][warp * 16], PADH);
            #pragma unroll
            for (int rt = 0; rt < 2; rt++)
                wmma::mma_sync(cw[rt], af[rt], bw, cw[rt]);
        }
        wmma::fragment<wmma::matrix_b, 16, 16, 16, __half, wmma::row_major> bo;
        wmma::load_matrix_sync(bo, &Boh[ks * 16][warp * 16], PADH);
        #pragma unroll
        for (int rt = 0; rt < 2; rt++)
            wmma::mma_sync(co[rt], af[rt], bo, co[rt]);
    }

    #pragma unroll
    for (int rt = 0; rt < 2; rt++) {
        if (hasW)
            wmma::store_matrix_sync(&Cs[rt * 16][warp * 16], cw[rt], 132, wmma::mem_row_major);
        wmma::store_matrix_sync(&Cs[rt * 16][64 + warp * 16], co[rt], 132, wmma::mem_row_major);
    }
    __syncthreads();

    if (hasW) {
        #pragma unroll
        for (int i = 0; i < 4; i++) {
            int idx = t + i * 128;
            int m = idx >> 4, c4 = (idx & 15) * 4;
            int row = rowBase + m;
            float s = g_ns[row];
            float4 v = *reinterpret_cast<const float4*>(&Cs[m][c4]);
            __half2* hp = &g_hs2[(size_t)row * 32 + (c4 >> 1)];
            hp[0] = __floats2half2_rn(v.x * s, v.y * s);
            hp[1] = __floats2half2_rn(v.z * s, v.w * s);
        }
    }
    #pragma unroll
    for (int i = 0; i < 4; i++) {
        int idx = t + i * 128;
        int m = idx >> 4, c4 = (idx & 15) * 4;
        int row = rowBase + m;
        float4 v = *reinterpret_cast<const float4*>(&Cs[m][64 + c4]);
        float4* yp = reinterpret_cast<float4*>(g_y + (size_t)row * HID + c4);
        if (firstY) {
            *yp = v;
        } else {
            float4 a = *yp;
            a.x += v.x; a.y += v.y; a.z += v.z; a.w += v.w;
            *yp = a;
        }
    }
}

// ---------------- launch ------------------------------------------------------
extern "C" void kernel_launch(void* const* d_in, const int* in_sizes, int n_in,
                              void* d_out, int out_size) {
    const float* feats = (const float*)d_in[0];
    const int*   src   = (const int*)d_in[1];
    const int*   dst   = (const int*)d_in[2];
    const float* W[5];
    const float* B[5];
    for (int i = 0; i < 5; i++) {
        W[i] = (const float*)d_in[3 + 2 * i];
        B[i] = (const float*)d_in[4 + 2 * i];
    }
    const float* Wout = (const float*)d_in[13];
    const float* bout = (const float*)d_in[14];
    float* out = (float*)d_out;

    const int TPB = 256;
    const int NB_V = (NV + TPB - 1) / TPB;      // 391
    const int NB_E = (NE + TPB - 1) / TPB;      // 6250
    const int NB_G = (NV * 32 + TPB - 1) / TPB; // 12500 (warp per node)

    // prologue (gemm0 kept in the ncu-sampled 4th slot)
    k_zero0<<<NB_V, TPB>>>();
    k_deg<<<NB_E, TPB>>>(src, dst);
    k_norm<<<NB_V, TPB>>>();
    k_gemm0<<<(NV + 63) / 64, 128>>>(feats, W[0]);

    // CSR build (independent of gemm0)
    k_scan1<<<NB_V, 256>>>();
    k_scan2<<<1, 512>>>();
    k_scan3<<<NB_V, TPB>>>();
    k_fill<<<NB_E, TPB>>>(src, dst);

    // 5 message-passing layers
    for (int l = 0; l < 5; l++) {
        k_gather_hs<<<NB_G, TPB>>>();
        int hasW = (l < 4) ? 1 : 0;
        k_gemm_fused<<<NV / TM, 128>>>(B[l],
                                       hasW ? W[l + 1] : W[0],
                                       Wout + (size_t)l * HID * 64,
                                       hasW, l == 0 ? 1 : 0);
    }

    // final aggregation straight into out (+bout)
    k_gather_out<<<NB_G, TPB>>>(out, bout);
}